// round 4
// baseline (speedup 1.0000x reference)
#include <cuda_runtime.h>
#include <cuda_bf16.h>
#include <cstdint>

// Problem constants
#define B_DIM  8
#define N_TOK  8192
#define C_IN   512
#define C_OUT  512

// Tiling
constexpr int M_TILE  = 128;
constexpr int N_TILE  = 128;
constexpr int KC      = 64;              // fp32 K elements per chunk
constexpr int NCHUNK  = C_IN / KC;       // 8
constexpr int THREADS = 256;             // 8 warps: 4 (M) x 2 (N)

// SMEM layout (dynamic)
constexpr int SM_BIAS = 0;               // 128 floats
constexpr int SM_DATA = 1024;

constexpr int TILE_BYTES = 128 * 128;     // 128 rows x 64 bf16 (128 B) = 16 KB
constexpr int OFF_AH = 0;
constexpr int OFF_AL = OFF_AH + TILE_BYTES;
constexpr int OFF_BH = OFF_AL + TILE_BYTES;
constexpr int OFF_BL = OFF_BH + TILE_BYTES;
constexpr int BUF_BYTES  = 4 * TILE_BYTES;              // 64 KB
constexpr int SMEM_TOTAL = SM_DATA + 2 * BUF_BYTES;     // ~132 KB

__device__ __forceinline__ uint32_t smem_u32(const void* p) {
    uint32_t a;
    asm("{ .reg .u64 t; cvta.to.shared.u64 t, %1; cvt.u32.u64 %0, t; }" : "=r"(a) : "l"(p));
    return a;
}

// ldmatrix x4 (non-transposed)
__device__ __forceinline__ void lds_frag4(uint32_t (&r)[4], uint32_t addr) {
    asm volatile("ldmatrix.sync.aligned.m8n8.x4.shared.b16 {%0,%1,%2,%3}, [%4];"
                 : "=r"(r[0]), "=r"(r[1]), "=r"(r[2]), "=r"(r[3]) : "r"(addr));
}

// D += A * B  (m16n8k16, bf16 in, f32 acc)
__device__ __forceinline__ void mma_bf16(float (&d)[4], const uint32_t (&a)[4],
                                         uint32_t b0, uint32_t b1) {
    asm volatile(
        "mma.sync.aligned.m16n8k16.row.col.f32.bf16.bf16.f32 "
        "{%0,%1,%2,%3}, {%4,%5,%6,%7}, {%8,%9}, {%0,%1,%2,%3};"
        : "+f"(d[0]), "+f"(d[1]), "+f"(d[2]), "+f"(d[3])
        : "r"(a[0]), "r"(a[1]), "r"(a[2]), "r"(a[3]), "r"(b0), "r"(b1));
}

// Split fp32 pair into packed bf16 hi (truncated) + bf16 lo (RN residual).
__device__ __forceinline__ void split_pair(float a, float b, uint32_t& h, uint32_t& l) {
    uint32_t ai = __float_as_uint(a), bi = __float_as_uint(b);
    h = __byte_perm(ai, bi, 0x7632);                       // {b_hi16, a_hi16}
    float ah = __uint_as_float(ai & 0xFFFF0000u);
    float bh = __uint_as_float(bi & 0xFFFF0000u);
    float ra = a - ah;
    float rb = b - bh;
    asm("cvt.rn.bf16x2.f32 %0, %1, %2;" : "=r"(l) : "f"(rb), "f"(ra));  // {rb, ra}
}

// Split 8 fp32 and store 16 B hi + 16 B lo to (pre-swizzled) SMEM addresses.
__device__ __forceinline__ void cvt_store8(uint32_t addr_h, uint32_t addr_l,
                                           float4 v0, float4 v1) {
    uint32_t h0, h1, h2, h3, l0, l1, l2, l3;
    split_pair(v0.x, v0.y, h0, l0);
    split_pair(v0.z, v0.w, h1, l1);
    split_pair(v1.x, v1.y, h2, l2);
    split_pair(v1.z, v1.w, h3, l3);
    asm volatile("st.shared.v4.b32 [%0], {%1,%2,%3,%4};"
                 :: "r"(addr_h), "r"(h0), "r"(h1), "r"(h2), "r"(h3) : "memory");
    asm volatile("st.shared.v4.b32 [%0], {%1,%2,%3,%4};"
                 :: "r"(addr_l), "r"(l0), "r"(l1), "r"(l2), "r"(l3) : "memory");
}

extern __shared__ char smem[];

__global__ void __launch_bounds__(THREADS, 1)
fc_batched_kernel(const float* __restrict__ x, const float* __restrict__ W,
                  const float* __restrict__ bias, float* __restrict__ out) {
    const uint32_t smem_base = smem_u32(smem);
    const int tid = threadIdx.x;
    const int lid = tid & 31;
    const int wid = tid >> 5;
    const int warp_m = wid & 3;      // 0..3 -> 32 rows each
    const int warp_n = wid >> 2;     // 0..1 -> 64 cols each

    const int m0  = blockIdx.x * M_TILE;
    const int n0g = blockIdx.y * N_TILE;
    const int bb  = blockIdx.z;

    // bias tile -> SMEM
    if (tid < N_TILE) {
        float bv = bias[bb * C_OUT + n0g + tid];
        asm volatile("st.shared.b32 [%0], %1;"
                     :: "r"(smem_base + SM_BIAS + tid * 4),
                        "r"(__float_as_uint(bv)) : "memory");
    }

    // ---- per-thread global load / SMEM store geometry ----
    // Each thread handles groups of 8 consecutive K values; group g = tid + it*256:
    //   row = g>>3 (it adds 32 rows), c0 = (g&7)*8.
    const int ldrow = tid >> 3;
    const int ldc0  = (tid & 7) * 8;
    const float* pA = x + ((size_t)bb * N_TOK + m0 + ldrow) * C_IN + ldc0;
    const float* pB = W + ((size_t)bb * C_OUT + n0g + ldrow) * C_IN + ldc0;
    // SW128 swizzled store offset (row&7 invariant across it since stride 32 rows)
    const uint32_t stsSw = (uint32_t)((ldrow * 128 + (tid & 7) * 16) ^ ((ldrow & 7) << 4));

    // ---- ldmatrix lane geometry ----
    const uint32_t xorv = (uint32_t)((lid & 7) << 4);
    const uint32_t khl  = (uint32_t)((lid >> 4) * 16);
    const uint32_t aoff = (uint32_t)((warp_m * 32 + (lid & 15)) * 128);
    const uint32_t boff = (uint32_t)((warp_n * 64 + (lid & 15)) * 128);

    float acc[2][8][4];
    #pragma unroll
    for (int mt = 0; mt < 2; ++mt)
        #pragma unroll
        for (int nt = 0; nt < 8; ++nt)
            #pragma unroll
            for (int i = 0; i < 4; ++i) acc[mt][nt][i] = 0.0f;

    const uint32_t buf[2] = { smem_base + SM_DATA, smem_base + SM_DATA + BUF_BYTES };

    // ---- prologue: chunk 0 -> buf0 ----
    #pragma unroll
    for (int it = 0; it < 4; ++it) {
        const float* g = pA + (size_t)it * 32 * C_IN;
        float4 v0 = *reinterpret_cast<const float4*>(g);
        float4 v1 = *reinterpret_cast<const float4*>(g + 4);
        cvt_store8(buf[0] + OFF_AH + stsSw + it * 4096,
                   buf[0] + OFF_AL + stsSw + it * 4096, v0, v1);
    }
    #pragma unroll
    for (int it = 0; it < 4; ++it) {
        const float* g = pB + (size_t)it * 32 * C_IN;
        float4 v0 = *reinterpret_cast<const float4*>(g);
        float4 v1 = *reinterpret_cast<const float4*>(g + 4);
        cvt_store8(buf[0] + OFF_BH + stsSw + it * 4096,
                   buf[0] + OFF_BL + stsSw + it * 4096, v0, v1);
    }
    __syncthreads();

    // one k16 slice: 12 ldmatrix + 48 mma
    auto do_slice = [&](uint32_t bc, uint32_t kx) {
        uint32_t ah[2][4], al[2][4], bh[4][4], bl[4][4];
        #pragma unroll
        for (int mt = 0; mt < 2; ++mt) {
            lds_frag4(ah[mt], bc + OFF_AH + aoff + mt * 2048 + kx);
            lds_frag4(al[mt], bc + OFF_AL + aoff + mt * 2048 + kx);
        }
        #pragma unroll
        for (int nt = 0; nt < 4; ++nt) {
            lds_frag4(bh[nt], bc + OFF_BH + boff + nt * 2048 + kx);
            lds_frag4(bl[nt], bc + OFF_BL + boff + nt * 2048 + kx);
        }
        #pragma unroll
        for (int mt = 0; mt < 2; ++mt)
            #pragma unroll
            for (int nt = 0; nt < 4; ++nt) {
                mma_bf16(acc[mt][nt * 2 + 0], ah[mt], bh[nt][0], bh[nt][2]);
                mma_bf16(acc[mt][nt * 2 + 1], ah[mt], bh[nt][1], bh[nt][3]);
                mma_bf16(acc[mt][nt * 2 + 0], al[mt], bh[nt][0], bh[nt][2]);
                mma_bf16(acc[mt][nt * 2 + 1], al[mt], bh[nt][1], bh[nt][3]);
                mma_bf16(acc[mt][nt * 2 + 0], ah[mt], bl[nt][0], bl[nt][2]);
                mma_bf16(acc[mt][nt * 2 + 1], ah[mt], bl[nt][1], bl[nt][3]);
            }
    };

    // ---- main loop over K chunks ----
    for (int kc = 0; kc < NCHUNK; ++kc) {
        const uint32_t bc = buf[kc & 1];
        const uint32_t bn = buf[(kc + 1) & 1];
        const bool pref = (kc + 1 < NCHUNK);
        const int  koff = (kc + 1) * KC;

        float4 va[8];
        if (pref) {
            #pragma unroll
            for (int it = 0; it < 4; ++it) {
                const float* g = pA + (size_t)it * 32 * C_IN + koff;
                va[2 * it]     = *reinterpret_cast<const float4*>(g);
                va[2 * it + 1] = *reinterpret_cast<const float4*>(g + 4);
            }
        }

        do_slice(bc, (0u * 32 + khl) ^ xorv);
        do_slice(bc, (1u * 32 + khl) ^ xorv);

        if (pref) {
            #pragma unroll
            for (int it = 0; it < 4; ++it)
                cvt_store8(bn + OFF_AH + stsSw + it * 4096,
                           bn + OFF_AL + stsSw + it * 4096, va[2 * it], va[2 * it + 1]);
            #pragma unroll
            for (int it = 0; it < 4; ++it) {
                const float* g = pB + (size_t)it * 32 * C_IN + koff;
                va[2 * it]     = *reinterpret_cast<const float4*>(g);
                va[2 * it + 1] = *reinterpret_cast<const float4*>(g + 4);
            }
        }

        do_slice(bc, (2u * 32 + khl) ^ xorv);
        do_slice(bc, (3u * 32 + khl) ^ xorv);

        if (pref) {
            #pragma unroll
            for (int it = 0; it < 4; ++it)
                cvt_store8(bn + OFF_BH + stsSw + it * 4096,
                           bn + OFF_BL + stsSw + it * 4096, va[2 * it], va[2 * it + 1]);
        }
        __syncthreads();
    }

    // ---- epilogue: acc + bias -> out ----
    const float* bias_s = reinterpret_cast<const float*>(smem + SM_BIAS);
    const int r0   = m0 + warp_m * 32 + (lid >> 2);
    const int cloc = warp_n * 64 + (lid & 3) * 2;

    #pragma unroll
    for (int mt = 0; mt < 2; ++mt) {
        #pragma unroll
        for (int nt = 0; nt < 8; ++nt) {
            const int cc = cloc + nt * 8;
            const float b0 = bias_s[cc];
            const float b1 = bias_s[cc + 1];
            const size_t base =
                ((size_t)bb * N_TOK + r0 + mt * 16) * C_OUT + n0g + cc;
            float2 v0 = make_float2(acc[mt][nt][0] + b0, acc[mt][nt][1] + b1);
            float2 v1 = make_float2(acc[mt][nt][2] + b0, acc[mt][nt][3] + b1);
            *reinterpret_cast<float2*>(out + base)             = v0;
            *reinterpret_cast<float2*>(out + base + 8 * C_OUT) = v1;
        }
    }
}

extern "C" void kernel_launch(void* const* d_in, const int* in_sizes, int n_in,
                              void* d_out, int out_size) {
    const float* x    = (const float*)d_in[0];
    const float* W    = (const float*)d_in[1];
    const float* bias = (const float*)d_in[2];
    float* out        = (float*)d_out;

    cudaFuncSetAttribute(fc_batched_kernel,
                         cudaFuncAttributeMaxDynamicSharedMemorySize, SMEM_TOTAL);

    dim3 grid(N_TOK / M_TILE, C_OUT / N_TILE, B_DIM);  // 64 x 4 x 8 = 2048 CTAs
    fc_batched_kernel<<<grid, THREADS, SMEM_TOTAL>>>(x, W, bias, out);
}

// round 8
// speedup vs baseline: 1.1586x; 1.1586x over previous
#include <cuda_runtime.h>
#include <cuda_bf16.h>
#include <cstdint>

// Problem constants
#define B_DIM  8
#define N_TOK  8192
#define C_IN   512
#define C_OUT  512

// Tiling
constexpr int M_TILE  = 128;
constexpr int N_TILE  = 256;
constexpr int KC      = 64;              // fp32 K elements per chunk
constexpr int NCHUNK  = C_IN / KC;       // 8
constexpr int THREADS = 512;             // 16 warps: 4 (M) x 4 (N)

// SMEM layout (dynamic)
constexpr int SM_BIAS = 0;               // 256 floats
constexpr int SM_DATA = 1024;

constexpr int A_BYTES = M_TILE * 128;     // 128 rows x 64 bf16 = 16 KB per (h|l)
constexpr int B_BYTES = N_TILE * 128;     // 256 rows x 64 bf16 = 32 KB per (h|l)
constexpr int OFF_AH = 0;
constexpr int OFF_AL = OFF_AH + A_BYTES;  // 16384
constexpr int OFF_BH = OFF_AL + A_BYTES;  // 32768
constexpr int OFF_BL = OFF_BH + B_BYTES;  // 65536
constexpr int BUF_BYTES  = OFF_BL + B_BYTES;            // 98304
constexpr int SMEM_TOTAL = SM_DATA + 2 * BUF_BYTES;     // 197632

__device__ __forceinline__ uint32_t smem_u32(const void* p) {
    uint32_t a;
    asm("{ .reg .u64 t; cvta.to.shared.u64 t, %1; cvt.u32.u64 %0, t; }" : "=r"(a) : "l"(p));
    return a;
}

// ldmatrix x4 (non-transposed)
__device__ __forceinline__ void lds_frag4(uint32_t (&r)[4], uint32_t addr) {
    asm volatile("ldmatrix.sync.aligned.m8n8.x4.shared.b16 {%0,%1,%2,%3}, [%4];"
                 : "=r"(r[0]), "=r"(r[1]), "=r"(r[2]), "=r"(r[3]) : "r"(addr));
}

// D += A * B  (m16n8k16, bf16 in, f32 acc)
__device__ __forceinline__ void mma_bf16(float (&d)[4], const uint32_t (&a)[4],
                                         uint32_t b0, uint32_t b1) {
    asm volatile(
        "mma.sync.aligned.m16n8k16.row.col.f32.bf16.bf16.f32 "
        "{%0,%1,%2,%3}, {%4,%5,%6,%7}, {%8,%9}, {%0,%1,%2,%3};"
        : "+f"(d[0]), "+f"(d[1]), "+f"(d[2]), "+f"(d[3])
        : "r"(a[0]), "r"(a[1]), "r"(a[2]), "r"(a[3]), "r"(b0), "r"(b1));
}

// Split fp32 pair into packed bf16 hi (truncated) + bf16 lo (RN residual).
__device__ __forceinline__ void split_pair(float a, float b, uint32_t& h, uint32_t& l) {
    uint32_t ai = __float_as_uint(a), bi = __float_as_uint(b);
    h = __byte_perm(ai, bi, 0x7632);                       // {b_hi16, a_hi16}
    float ah = __uint_as_float(ai & 0xFFFF0000u);
    float bh = __uint_as_float(bi & 0xFFFF0000u);
    float ra = a - ah;
    float rb = b - bh;
    asm("cvt.rn.bf16x2.f32 %0, %1, %2;" : "=r"(l) : "f"(rb), "f"(ra));  // {rb, ra}
}

// Split 8 fp32 and store 16 B hi + 16 B lo to (pre-swizzled) SMEM addresses.
__device__ __forceinline__ void cvt_store8(uint32_t addr_h, uint32_t addr_l,
                                           float4 v0, float4 v1) {
    uint32_t h0, h1, h2, h3, l0, l1, l2, l3;
    split_pair(v0.x, v0.y, h0, l0);
    split_pair(v0.z, v0.w, h1, l1);
    split_pair(v1.x, v1.y, h2, l2);
    split_pair(v1.z, v1.w, h3, l3);
    asm volatile("st.shared.v4.b32 [%0], {%1,%2,%3,%4};"
                 :: "r"(addr_h), "r"(h0), "r"(h1), "r"(h2), "r"(h3) : "memory");
    asm volatile("st.shared.v4.b32 [%0], {%1,%2,%3,%4};"
                 :: "r"(addr_l), "r"(l0), "r"(l1), "r"(l2), "r"(l3) : "memory");
}

extern __shared__ char smem[];

__global__ void __launch_bounds__(THREADS, 1)
fc_batched_kernel(const float* __restrict__ x, const float* __restrict__ W,
                  const float* __restrict__ bias, float* __restrict__ out) {
    const uint32_t smem_base = smem_u32(smem);
    const int tid = threadIdx.x;
    const int lid = tid & 31;
    const int wid = tid >> 5;
    const int warp_m = wid & 3;      // 0..3 -> 32 rows each
    const int warp_n = wid >> 2;     // 0..3 -> 64 cols each

    const int m0  = blockIdx.x * M_TILE;
    const int n0g = blockIdx.y * N_TILE;
    const int bb  = blockIdx.z;

    // bias tile -> SMEM
    if (tid < N_TILE) {
        float bv = bias[bb * C_OUT + n0g + tid];
        asm volatile("st.shared.b32 [%0], %1;"
                     :: "r"(smem_base + SM_BIAS + tid * 4),
                        "r"(__float_as_uint(bv)) : "memory");
    }

    // ---- per-thread global load / SMEM store geometry ----
    // Group of 8 consecutive K floats: g = tid + it*512 -> row = g>>3 (it adds 64 rows),
    // c0 = (g&7)*8. A: it 0..1 (128 rows). B: it 0..3 (256 rows).
    const int ldrow = tid >> 3;             // 0..63
    const int ldc0  = (tid & 7) * 8;
    const float* pA = x + ((size_t)bb * N_TOK + m0 + ldrow) * C_IN + ldc0;
    const float* pB = W + ((size_t)bb * C_OUT + n0g + ldrow) * C_IN + ldc0;
    // SW128 swizzled store offset; row&7 invariant across it (stride 64 rows)
    const uint32_t stsSw = (uint32_t)((ldrow * 128 + (tid & 7) * 16) ^ ((ldrow & 7) << 4));

    // ---- ldmatrix lane geometry ----
    const uint32_t xorv = (uint32_t)((lid & 7) << 4);
    const uint32_t khl  = (uint32_t)((lid >> 4) * 16);
    const uint32_t aoff = (uint32_t)((warp_m * 32 + (lid & 15)) * 128);
    const uint32_t boff = (uint32_t)((warp_n * 64 + (lid & 15)) * 128);

    float acc[2][8][4];
    #pragma unroll
    for (int mt = 0; mt < 2; ++mt)
        #pragma unroll
        for (int nt = 0; nt < 8; ++nt)
            #pragma unroll
            for (int i = 0; i < 4; ++i) acc[mt][nt][i] = 0.0f;

    const uint32_t buf[2] = { smem_base + SM_DATA, smem_base + SM_DATA + BUF_BYTES };

    // ---- prologue: chunk 0 -> buf0 ----
    #pragma unroll
    for (int it = 0; it < 2; ++it) {
        const float* g = pA + (size_t)it * 64 * C_IN;
        float4 v0 = *reinterpret_cast<const float4*>(g);
        float4 v1 = *reinterpret_cast<const float4*>(g + 4);
        cvt_store8(buf[0] + OFF_AH + stsSw + it * 8192,
                   buf[0] + OFF_AL + stsSw + it * 8192, v0, v1);
    }
    #pragma unroll
    for (int it = 0; it < 4; ++it) {
        const float* g = pB + (size_t)it * 64 * C_IN;
        float4 v0 = *reinterpret_cast<const float4*>(g);
        float4 v1 = *reinterpret_cast<const float4*>(g + 4);
        cvt_store8(buf[0] + OFF_BH + stsSw + it * 8192,
                   buf[0] + OFF_BL + stsSw + it * 8192, v0, v1);
    }
    __syncthreads();

    // One k16 slice: A frags once, B frags in 2 halves; product terms interleaved
    // (hh, lh, hl) so each acc's 3-MMA RAW chain is spaced by 12 independent MMAs.
    auto do_slice = [&](uint32_t bc, uint32_t kx) {
        uint32_t ah[2][4], al[2][4];
        #pragma unroll
        for (int mt = 0; mt < 2; ++mt) {
            lds_frag4(ah[mt], bc + OFF_AH + aoff + mt * 2048 + kx);
            lds_frag4(al[mt], bc + OFF_AL + aoff + mt * 2048 + kx);
        }
        #pragma unroll
        for (int nh = 0; nh < 2; ++nh) {
            uint32_t bh[2][4], bl[2][4];
            #pragma unroll
            for (int j = 0; j < 2; ++j) {
                lds_frag4(bh[j], bc + OFF_BH + boff + (nh * 2 + j) * 2048 + kx);
                lds_frag4(bl[j], bc + OFF_BL + boff + (nh * 2 + j) * 2048 + kx);
            }
            // term 1: ah * bh
            #pragma unroll
            for (int mt = 0; mt < 2; ++mt)
                #pragma unroll
                for (int j = 0; j < 2; ++j) {
                    const int nt = nh * 2 + j;
                    mma_bf16(acc[mt][nt * 2 + 0], ah[mt], bh[j][0], bh[j][2]);
                    mma_bf16(acc[mt][nt * 2 + 1], ah[mt], bh[j][1], bh[j][3]);
                }
            // term 2: al * bh
            #pragma unroll
            for (int mt = 0; mt < 2; ++mt)
                #pragma unroll
                for (int j = 0; j < 2; ++j) {
                    const int nt = nh * 2 + j;
                    mma_bf16(acc[mt][nt * 2 + 0], al[mt], bh[j][0], bh[j][2]);
                    mma_bf16(acc[mt][nt * 2 + 1], al[mt], bh[j][1], bh[j][3]);
                }
            // term 3: ah * bl
            #pragma unroll
            for (int mt = 0; mt < 2; ++mt)
                #pragma unroll
                for (int j = 0; j < 2; ++j) {
                    const int nt = nh * 2 + j;
                    mma_bf16(acc[mt][nt * 2 + 0], ah[mt], bl[j][0], bl[j][2]);
                    mma_bf16(acc[mt][nt * 2 + 1], ah[mt], bl[j][1], bl[j][3]);
                }
        }
    };

    // ---- main loop over K chunks ----
    for (int kc = 0; kc < NCHUNK; ++kc) {
        const uint32_t bc = buf[kc & 1];
        const uint32_t bn = buf[(kc + 1) & 1];
        const bool pref = (kc + 1 < NCHUNK);
        const int  koff = (kc + 1) * KC;

        float4 va[4];   // at most 16 registers of prefetch live at a time

        // prefetch A (2 groups)
        if (pref) {
            #pragma unroll
            for (int it = 0; it < 2; ++it) {
                const float* g = pA + (size_t)it * 64 * C_IN + koff;
                va[2 * it]     = *reinterpret_cast<const float4*>(g);
                va[2 * it + 1] = *reinterpret_cast<const float4*>(g + 4);
            }
        }

        do_slice(bc, (0u * 32 + khl) ^ xorv);
        do_slice(bc, (1u * 32 + khl) ^ xorv);

        if (pref) {
            #pragma unroll
            for (int it = 0; it < 2; ++it)
                cvt_store8(bn + OFF_AH + stsSw + it * 8192,
                           bn + OFF_AL + stsSw + it * 8192, va[2 * it], va[2 * it + 1]);
            // prefetch B first half (2 groups)
            #pragma unroll
            for (int it = 0; it < 2; ++it) {
                const float* g = pB + (size_t)it * 64 * C_IN + koff;
                va[2 * it]     = *reinterpret_cast<const float4*>(g);
                va[2 * it + 1] = *reinterpret_cast<const float4*>(g + 4);
            }
        }

        do_slice(bc, (2u * 32 + khl) ^ xorv);

        if (pref) {
            #pragma unroll
            for (int it = 0; it < 2; ++it)
                cvt_store8(bn + OFF_BH + stsSw + it * 8192,
                           bn + OFF_BL + stsSw + it * 8192, va[2 * it], va[2 * it + 1]);
            // prefetch B second half (2 groups)
            #pragma unroll
            for (int it = 2; it < 4; ++it) {
                const float* g = pB + (size_t)it * 64 * C_IN + koff;
                va[2 * (it - 2)]     = *reinterpret_cast<const float4*>(g);
                va[2 * (it - 2) + 1] = *reinterpret_cast<const float4*>(g + 4);
            }
        }

        do_slice(bc, (3u * 32 + khl) ^ xorv);

        if (pref) {
            #pragma unroll
            for (int it = 2; it < 4; ++it)
                cvt_store8(bn + OFF_BH + stsSw + it * 8192,
                           bn + OFF_BL + stsSw + it * 8192,
                           va[2 * (it - 2)], va[2 * (it - 2) + 1]);
        }
        __syncthreads();
    }

    // ---- epilogue: acc + bias -> out ----
    const float* bias_s = reinterpret_cast<const float*>(smem + SM_BIAS);
    const int r0   = m0 + warp_m * 32 + (lid >> 2);
    const int cloc = warp_n * 64 + (lid & 3) * 2;

    #pragma unroll
    for (int mt = 0; mt < 2; ++mt) {
        #pragma unroll
        for (int nt = 0; nt < 8; ++nt) {
            const int cc = cloc + nt * 8;
            const float b0 = bias_s[cc];
            const float b1 = bias_s[cc + 1];
            const size_t base =
                ((size_t)bb * N_TOK + r0 + mt * 16) * C_OUT + n0g + cc;
            float2 v0 = make_float2(acc[mt][nt][0] + b0, acc[mt][nt][1] + b1);
            float2 v1 = make_float2(acc[mt][nt][2] + b0, acc[mt][nt][3] + b1);
            *reinterpret_cast<float2*>(out + base)             = v0;
            *reinterpret_cast<float2*>(out + base + 8 * C_OUT) = v1;
        }
    }
}

extern "C" void kernel_launch(void* const* d_in, const int* in_sizes, int n_in,
                              void* d_out, int out_size) {
    const float* x    = (const float*)d_in[0];
    const float* W    = (const float*)d_in[1];
    const float* bias = (const float*)d_in[2];
    float* out        = (float*)d_out;

    cudaFuncSetAttribute(fc_batched_kernel,
                         cudaFuncAttributeMaxDynamicSharedMemorySize, SMEM_TOTAL);

    dim3 grid(N_TOK / M_TILE, C_OUT / N_TILE, B_DIM);  // 64 x 2 x 8 = 1024 CTAs
    fc_batched_kernel<<<grid, THREADS, SMEM_TOTAL>>>(x, W, bias, out);
}

// round 13
// speedup vs baseline: 2.3473x; 2.0261x over previous
#include <cuda_runtime.h>
#include <cuda_fp16.h>
#include <cstdint>

// Problem constants
#define B_DIM  8
#define N_TOK  8192
#define C_IN   512
#define C_OUT  512

// GEMM tiling
constexpr int M_TILE  = 128;
constexpr int N_TILE  = 256;
constexpr int KC      = 64;              // K elems per chunk (128 B fp16 = SW128 row)
constexpr int NCHUNK  = C_IN / KC;       // 8
constexpr int THREADS = 512;             // 16 warps: 4 (M) x 4 (N)
constexpr int STAGES  = 4;

// fp16 scratch (pass 1 output)
constexpr size_t X_ELEMS = (size_t)B_DIM * N_TOK * C_IN;   // 33,554,432
constexpr size_t W_ELEMS = (size_t)B_DIM * C_OUT * C_IN;   //  2,097,152
__device__ __align__(16) __half g_xh[X_ELEMS];
__device__ __align__(16) __half g_wh[W_ELEMS];

// SMEM layout (pass 2)
constexpr int SM_BIAS = 0;               // 256 floats
constexpr int SM_DATA = 1024;
constexpr int A_BYTES = M_TILE * 128;    // 16 KB
constexpr int B_BYTES = N_TILE * 128;    // 32 KB
constexpr int STG_BYTES = A_BYTES + B_BYTES;            // 49152
constexpr int SMEM_TOTAL = SM_DATA + STAGES * STG_BYTES; // 197632

__device__ __forceinline__ uint32_t smem_u32(const void* p) {
    uint32_t a;
    asm("{ .reg .u64 t; cvta.to.shared.u64 t, %1; cvt.u32.u64 %0, t; }" : "=r"(a) : "l"(p));
    return a;
}

__device__ __forceinline__ void lds_frag4(uint32_t (&r)[4], uint32_t addr) {
    asm volatile("ldmatrix.sync.aligned.m8n8.x4.shared.b16 {%0,%1,%2,%3}, [%4];"
                 : "=r"(r[0]), "=r"(r[1]), "=r"(r[2]), "=r"(r[3]) : "r"(addr));
}

// D += A * B  (m16n8k16, fp16 in, f32 acc)
__device__ __forceinline__ void mma_f16(float (&d)[4], const uint32_t (&a)[4],
                                        uint32_t b0, uint32_t b1) {
    asm volatile(
        "mma.sync.aligned.m16n8k16.row.col.f32.f16.f16.f32 "
        "{%0,%1,%2,%3}, {%4,%5,%6,%7}, {%8,%9}, {%0,%1,%2,%3};"
        : "+f"(d[0]), "+f"(d[1]), "+f"(d[2]), "+f"(d[3])
        : "r"(a[0]), "r"(a[1]), "r"(a[2]), "r"(a[3]), "r"(b0), "r"(b1));
}

__device__ __forceinline__ void cp16(uint32_t dst, const void* src) {
    asm volatile("cp.async.cg.shared.global [%0], [%1], 16;" :: "r"(dst), "l"(src));
}
#define CP_COMMIT()  asm volatile("cp.async.commit_group;" ::: "memory")
#define CP_WAIT3()   asm volatile("cp.async.wait_group 3;" ::: "memory")

// ===================== Pass 1: fp32 -> fp16 convert =====================
__global__ void __launch_bounds__(512)
cvt_kernel(const float* __restrict__ x, const float* __restrict__ W) {
    const size_t g = (size_t)blockIdx.x * blockDim.x + threadIdx.x;  // group of 8 elems
    constexpr size_t XG = X_ELEMS / 8;   // 4194304
    constexpr size_t WG = W_ELEMS / 8;   //  262144

    const float4* src;
    uint4* dst;
    if (g < XG) {
        src = reinterpret_cast<const float4*>(x) + g * 2;
        dst = reinterpret_cast<uint4*>(g_xh) + g;
    } else if (g < XG + WG) {
        const size_t gw = g - XG;
        src = reinterpret_cast<const float4*>(W) + gw * 2;
        dst = reinterpret_cast<uint4*>(g_wh) + gw;
    } else {
        return;
    }
    float4 v0 = src[0];
    float4 v1 = src[1];
    __half2 h0 = __float22half2_rn(make_float2(v0.x, v0.y));
    __half2 h1 = __float22half2_rn(make_float2(v0.z, v0.w));
    __half2 h2 = __float22half2_rn(make_float2(v1.x, v1.y));
    __half2 h3 = __float22half2_rn(make_float2(v1.z, v1.w));
    uint4 o;
    o.x = *reinterpret_cast<uint32_t*>(&h0);
    o.y = *reinterpret_cast<uint32_t*>(&h1);
    o.z = *reinterpret_cast<uint32_t*>(&h2);
    o.w = *reinterpret_cast<uint32_t*>(&h3);
    *dst = o;
}

// ===================== Pass 2: fp16 GEMM =====================
extern __shared__ char smem[];

__global__ void __launch_bounds__(THREADS, 1)
fc_gemm_kernel(const float* __restrict__ bias, float* __restrict__ out) {
    const uint32_t smem_base = smem_u32(smem);
    const int tid = threadIdx.x;
    const int lid = tid & 31;
    const int wid = tid >> 5;
    const int warp_m = wid & 3;      // 0..3 -> 32 rows
    const int warp_n = wid >> 2;     // 0..3 -> 64 cols

    const int m0  = blockIdx.x * M_TILE;
    const int n0g = blockIdx.y * N_TILE;
    const int bb  = blockIdx.z;

    // bias tile -> SMEM
    if (tid < N_TILE) {
        float bv = bias[bb * C_OUT + n0g + tid];
        asm volatile("st.shared.b32 [%0], %1;"
                     :: "r"(smem_base + SM_BIAS + tid * 4),
                        "r"(__float_as_uint(bv)) : "memory");
    }

    // ---- cp.async geometry ----
    // granule = 16 B (8 fp16 of K). g = tid + j*512: row = g>>3, c16 = g&7.
    const int ldrow = tid >> 3;      // 0..63 (j adds 64 rows)
    const int ldc16 = tid & 7;
    const __half* xbase = g_xh + ((size_t)bb * N_TOK + m0 + ldrow) * C_IN + ldc16 * 8;
    const __half* wbase = g_wh + ((size_t)bb * C_OUT + n0g + ldrow) * C_IN + ldc16 * 8;
    const uint32_t stsSw =
        (uint32_t)((ldrow * 128 + ldc16 * 16) ^ ((ldrow & 7) << 4));

    // ---- ldmatrix lane geometry ----
    const uint32_t xorv = (uint32_t)((lid & 7) << 4);
    const uint32_t khl  = (uint32_t)((lid >> 4) * 16);
    const uint32_t aoff = (uint32_t)((warp_m * 32 + (lid & 15)) * 128);
    const uint32_t boff = (uint32_t)((warp_n * 64 + (lid & 15)) * 128);

    float acc[2][8][4];
    #pragma unroll
    for (int mt = 0; mt < 2; ++mt)
        #pragma unroll
        for (int nt = 0; nt < 8; ++nt)
            #pragma unroll
            for (int i = 0; i < 4; ++i) acc[mt][nt][i] = 0.0f;

    // issue one chunk's loads into a stage
    auto issue = [&](int kc, int stg) {
        const uint32_t sb = smem_base + SM_DATA + stg * STG_BYTES;
        #pragma unroll
        for (int j = 0; j < 2; ++j)                       // A: 128 rows
            cp16(sb + stsSw + j * 8192,
                 xbase + (size_t)j * 64 * C_IN + kc * KC);
        #pragma unroll
        for (int j = 0; j < 4; ++j)                       // B: 256 rows
            cp16(sb + A_BYTES + stsSw + j * 8192,
                 wbase + (size_t)j * 64 * C_IN + kc * KC);
    };

    // prologue: stages 0..2
    #pragma unroll
    for (int kc = 0; kc < STAGES - 1; ++kc) {
        issue(kc, kc);
        CP_COMMIT();
    }

    // one k16 slice: 6 ldmatrix + 16 mma
    auto do_slice = [&](uint32_t bc, uint32_t kx) {
        uint32_t a[2][4], b[4][4];
        #pragma unroll
        for (int mt = 0; mt < 2; ++mt)
            lds_frag4(a[mt], bc + aoff + mt * 2048 + kx);
        #pragma unroll
        for (int nt = 0; nt < 4; ++nt)
            lds_frag4(b[nt], bc + A_BYTES + boff + nt * 2048 + kx);
        #pragma unroll
        for (int mt = 0; mt < 2; ++mt)
            #pragma unroll
            for (int nt = 0; nt < 4; ++nt) {
                mma_f16(acc[mt][nt * 2 + 0], a[mt], b[nt][0], b[nt][2]);
                mma_f16(acc[mt][nt * 2 + 1], a[mt], b[nt][1], b[nt][3]);
            }
    };

    // ---- main loop ----
    for (int kc = 0; kc < NCHUNK; ++kc) {
        if (kc + STAGES - 1 < NCHUNK)
            issue(kc + STAGES - 1, (kc + STAGES - 1) & (STAGES - 1));
        CP_COMMIT();                       // always commit (empty groups keep count uniform)
        CP_WAIT3();                        // <=3 pending -> chunk kc landed
        __syncthreads();

        const uint32_t bc = smem_base + SM_DATA + (kc & (STAGES - 1)) * STG_BYTES;
        do_slice(bc, (0u * 32 + khl) ^ xorv);
        do_slice(bc, (1u * 32 + khl) ^ xorv);
        do_slice(bc, (2u * 32 + khl) ^ xorv);
        do_slice(bc, (3u * 32 + khl) ^ xorv);
        __syncthreads();                   // stage free for reuse next iteration
    }

    // ---- epilogue: acc + bias -> out ----
    const float* bias_s = reinterpret_cast<const float*>(smem + SM_BIAS);
    const int r0   = m0 + warp_m * 32 + (lid >> 2);
    const int cloc = warp_n * 64 + (lid & 3) * 2;

    #pragma unroll
    for (int mt = 0; mt < 2; ++mt) {
        #pragma unroll
        for (int nt = 0; nt < 8; ++nt) {
            const int cc = cloc + nt * 8;
            const float b0 = bias_s[cc];
            const float b1 = bias_s[cc + 1];
            const size_t base =
                ((size_t)bb * N_TOK + r0 + mt * 16) * C_OUT + n0g + cc;
            float2 v0 = make_float2(acc[mt][nt][0] + b0, acc[mt][nt][1] + b1);
            float2 v1 = make_float2(acc[mt][nt][2] + b0, acc[mt][nt][3] + b1);
            *reinterpret_cast<float2*>(out + base)             = v0;
            *reinterpret_cast<float2*>(out + base + 8 * C_OUT) = v1;
        }
    }
}

extern "C" void kernel_launch(void* const* d_in, const int* in_sizes, int n_in,
                              void* d_out, int out_size) {
    const float* x    = (const float*)d_in[0];
    const float* W    = (const float*)d_in[1];
    const float* bias = (const float*)d_in[2];
    float* out        = (float*)d_out;

    cudaFuncSetAttribute(fc_gemm_kernel,
                         cudaFuncAttributeMaxDynamicSharedMemorySize, SMEM_TOTAL);

    // Pass 1: fp32 -> fp16 (x and W)
    constexpr size_t NGROUPS = X_ELEMS / 8 + W_ELEMS / 8;   // 4,456,448
    cvt_kernel<<<(unsigned)(NGROUPS / 512), 512>>>(x, W);

    // Pass 2: fp16 GEMM + bias
    dim3 grid(N_TOK / M_TILE, C_OUT / N_TILE, B_DIM);  // 64 x 2 x 8 = 1024
    fc_gemm_kernel<<<grid, THREADS, SMEM_TOTAL>>>(bias, out);
}

// round 15
// speedup vs baseline: 2.5635x; 1.0921x over previous
#include <cuda_runtime.h>
#include <cuda_fp16.h>
#include <cstdint>

// Problem constants
#define B_DIM  8
#define N_TOK  8192
#define C_IN   512
#define C_OUT  512

// GEMM tiling: CTA 128x128, 8 warps (4M x 2N), 2 CTAs/SM
constexpr int M_TILE  = 128;
constexpr int N_TILE  = 128;
constexpr int KC      = 64;              // K elems per chunk (128 B fp16 = SW128 row)
constexpr int NCHUNK  = C_IN / KC;       // 8
constexpr int THREADS = 256;
constexpr int STAGES  = 3;

// fp16 scratch (pass 1 output)
constexpr size_t X_ELEMS = (size_t)B_DIM * N_TOK * C_IN;   // 33,554,432
constexpr size_t W_ELEMS = (size_t)B_DIM * C_OUT * C_IN;   //  2,097,152
__device__ __align__(16) __half g_xh[X_ELEMS];
__device__ __align__(16) __half g_wh[W_ELEMS];

// SMEM layout (pass 2)
constexpr int SM_BIAS = 0;               // 128 floats
constexpr int SM_DATA = 1024;
constexpr int A_BYTES = M_TILE * 128;    // 16 KB
constexpr int B_BYTES = N_TILE * 128;    // 16 KB
constexpr int STG_BYTES = A_BYTES + B_BYTES;             // 32768
constexpr int SMEM_TOTAL = SM_DATA + STAGES * STG_BYTES; // 99328

__device__ __forceinline__ uint32_t smem_u32(const void* p) {
    uint32_t a;
    asm("{ .reg .u64 t; cvta.to.shared.u64 t, %1; cvt.u32.u64 %0, t; }" : "=r"(a) : "l"(p));
    return a;
}

__device__ __forceinline__ void lds_frag4(uint32_t (&r)[4], uint32_t addr) {
    asm volatile("ldmatrix.sync.aligned.m8n8.x4.shared.b16 {%0,%1,%2,%3}, [%4];"
                 : "=r"(r[0]), "=r"(r[1]), "=r"(r[2]), "=r"(r[3]) : "r"(addr));
}

// D += A * B  (m16n8k16, fp16 in, f32 acc)
__device__ __forceinline__ void mma_f16(float (&d)[4], const uint32_t (&a)[4],
                                        uint32_t b0, uint32_t b1) {
    asm volatile(
        "mma.sync.aligned.m16n8k16.row.col.f32.f16.f16.f32 "
        "{%0,%1,%2,%3}, {%4,%5,%6,%7}, {%8,%9}, {%0,%1,%2,%3};"
        : "+f"(d[0]), "+f"(d[1]), "+f"(d[2]), "+f"(d[3])
        : "r"(a[0]), "r"(a[1]), "r"(a[2]), "r"(a[3]), "r"(b0), "r"(b1));
}

__device__ __forceinline__ void cp16(uint32_t dst, const void* src) {
    asm volatile("cp.async.cg.shared.global [%0], [%1], 16;" :: "r"(dst), "l"(src));
}
#define CP_COMMIT()  asm volatile("cp.async.commit_group;" ::: "memory")
#define CP_WAIT2()   asm volatile("cp.async.wait_group 2;" ::: "memory")

// ===================== Pass 1: fp32 -> fp16 convert =====================
__global__ void __launch_bounds__(512)
cvt_kernel(const float* __restrict__ x, const float* __restrict__ W) {
    const size_t g = (size_t)blockIdx.x * blockDim.x + threadIdx.x;  // group of 8 elems
    constexpr size_t XG = X_ELEMS / 8;   // 4194304
    constexpr size_t WG = W_ELEMS / 8;   //  262144

    const float4* src;
    uint4* dst;
    if (g < XG) {
        src = reinterpret_cast<const float4*>(x) + g * 2;
        dst = reinterpret_cast<uint4*>(g_xh) + g;
    } else if (g < XG + WG) {
        const size_t gw = g - XG;
        src = reinterpret_cast<const float4*>(W) + gw * 2;
        dst = reinterpret_cast<uint4*>(g_wh) + gw;
    } else {
        return;
    }
    float4 v0 = src[0];
    float4 v1 = src[1];
    __half2 h0 = __float22half2_rn(make_float2(v0.x, v0.y));
    __half2 h1 = __float22half2_rn(make_float2(v0.z, v0.w));
    __half2 h2 = __float22half2_rn(make_float2(v1.x, v1.y));
    __half2 h3 = __float22half2_rn(make_float2(v1.z, v1.w));
    uint4 o;
    o.x = *reinterpret_cast<uint32_t*>(&h0);
    o.y = *reinterpret_cast<uint32_t*>(&h1);
    o.z = *reinterpret_cast<uint32_t*>(&h2);
    o.w = *reinterpret_cast<uint32_t*>(&h3);
    *dst = o;
}

// ===================== Pass 2: fp16 GEMM =====================
extern __shared__ char smem[];

__global__ void __launch_bounds__(THREADS, 2)
fc_gemm_kernel(const float* __restrict__ bias, float* __restrict__ out) {
    const uint32_t smem_base = smem_u32(smem);
    const int tid = threadIdx.x;
    const int lid = tid & 31;
    const int wid = tid >> 5;
    const int warp_m = wid & 3;      // 0..3 -> 32 rows
    const int warp_n = wid >> 2;     // 0..1 -> 64 cols

    const int m0  = blockIdx.x * M_TILE;
    const int n0g = blockIdx.y * N_TILE;
    const int bb  = blockIdx.z;

    // bias tile -> SMEM
    if (tid < N_TILE) {
        float bv = bias[bb * C_OUT + n0g + tid];
        asm volatile("st.shared.b32 [%0], %1;"
                     :: "r"(smem_base + SM_BIAS + tid * 4),
                        "r"(__float_as_uint(bv)) : "memory");
    }

    // ---- cp.async geometry ----
    // granule = 16 B (8 fp16 of K). g = tid + j*256: row = g>>3, c16 = g&7.
    const int ldrow = tid >> 3;      // 0..31 (j adds 32 rows)
    const int ldc16 = tid & 7;
    const __half* xbase = g_xh + ((size_t)bb * N_TOK + m0 + ldrow) * C_IN + ldc16 * 8;
    const __half* wbase = g_wh + ((size_t)bb * C_OUT + n0g + ldrow) * C_IN + ldc16 * 8;
    const uint32_t stsSw =
        (uint32_t)((ldrow * 128 + ldc16 * 16) ^ ((ldrow & 7) << 4));

    // ---- ldmatrix lane geometry ----
    const uint32_t xorv = (uint32_t)((lid & 7) << 4);
    const uint32_t khl  = (uint32_t)((lid >> 4) * 16);
    const uint32_t aoff = (uint32_t)((warp_m * 32 + (lid & 15)) * 128);
    const uint32_t boff = (uint32_t)((warp_n * 64 + (lid & 15)) * 128);

    float acc[2][8][4];
    #pragma unroll
    for (int mt = 0; mt < 2; ++mt)
        #pragma unroll
        for (int nt = 0; nt < 8; ++nt)
            #pragma unroll
            for (int i = 0; i < 4; ++i) acc[mt][nt][i] = 0.0f;

    // issue one chunk's loads into a stage (4 A granule-rows + 4 B granule-rows)
    auto issue = [&](int kc, int stg) {
        const uint32_t sb = smem_base + SM_DATA + stg * STG_BYTES;
        #pragma unroll
        for (int j = 0; j < 4; ++j)                       // A: 128 rows
            cp16(sb + stsSw + j * 4096,
                 xbase + (size_t)j * 32 * C_IN + kc * KC);
        #pragma unroll
        for (int j = 0; j < 4; ++j)                       // B: 128 rows
            cp16(sb + A_BYTES + stsSw + j * 4096,
                 wbase + (size_t)j * 32 * C_IN + kc * KC);
    };

    // prologue: chunks 0..1 into stages 0..1
    issue(0, 0); CP_COMMIT();
    issue(1, 1); CP_COMMIT();

    // one k16 slice: 6 ldmatrix + 16 mma
    auto do_slice = [&](uint32_t bc, uint32_t kx) {
        uint32_t a[2][4], b[4][4];
        #pragma unroll
        for (int mt = 0; mt < 2; ++mt)
            lds_frag4(a[mt], bc + aoff + mt * 2048 + kx);
        #pragma unroll
        for (int nt = 0; nt < 4; ++nt)
            lds_frag4(b[nt], bc + A_BYTES + boff + nt * 2048 + kx);
        #pragma unroll
        for (int mt = 0; mt < 2; ++mt)
            #pragma unroll
            for (int nt = 0; nt < 4; ++nt) {
                mma_f16(acc[mt][nt * 2 + 0], a[mt], b[nt][0], b[nt][2]);
                mma_f16(acc[mt][nt * 2 + 1], a[mt], b[nt][1], b[nt][3]);
            }
    };

    // ---- main loop ----
    // iter kc: issue chunk kc+2 into stage (kc+2)%3 (consumed in iter kc-1,
    // protected by end-of-loop sync), then wait for chunk kc and compute.
    int stg = 0;
    for (int kc = 0; kc < NCHUNK; ++kc) {
        if (kc + 2 < NCHUNK) {
            int s2 = stg + 2; if (s2 >= STAGES) s2 -= STAGES;
            issue(kc + 2, s2);
        }
        CP_COMMIT();                 // keep group count uniform
        CP_WAIT2();                  // <=2 pending -> chunk kc landed
        __syncthreads();

        const uint32_t bc = smem_base + SM_DATA + stg * STG_BYTES;
        do_slice(bc, (0u * 32 + khl) ^ xorv);
        do_slice(bc, (1u * 32 + khl) ^ xorv);
        do_slice(bc, (2u * 32 + khl) ^ xorv);
        do_slice(bc, (3u * 32 + khl) ^ xorv);
        __syncthreads();             // stage free for reuse

        if (++stg == STAGES) stg = 0;
    }

    // ---- epilogue: acc + bias -> out ----
    const float* bias_s = reinterpret_cast<const float*>(smem + SM_BIAS);
    const int r0   = m0 + warp_m * 32 + (lid >> 2);
    const int cloc = warp_n * 64 + (lid & 3) * 2;

    #pragma unroll
    for (int mt = 0; mt < 2; ++mt) {
        #pragma unroll
        for (int nt = 0; nt < 8; ++nt) {
            const int cc = cloc + nt * 8;
            const float b0 = bias_s[cc];
            const float b1 = bias_s[cc + 1];
            const size_t base =
                ((size_t)bb * N_TOK + r0 + mt * 16) * C_OUT + n0g + cc;
            float2 v0 = make_float2(acc[mt][nt][0] + b0, acc[mt][nt][1] + b1);
            float2 v1 = make_float2(acc[mt][nt][2] + b0, acc[mt][nt][3] + b1);
            *reinterpret_cast<float2*>(out + base)             = v0;
            *reinterpret_cast<float2*>(out + base + 8 * C_OUT) = v1;
        }
    }
}

extern "C" void kernel_launch(void* const* d_in, const int* in_sizes, int n_in,
                              void* d_out, int out_size) {
    const float* x    = (const float*)d_in[0];
    const float* W    = (const float*)d_in[1];
    const float* bias = (const float*)d_in[2];
    float* out        = (float*)d_out;

    cudaFuncSetAttribute(fc_gemm_kernel,
                         cudaFuncAttributeMaxDynamicSharedMemorySize, SMEM_TOTAL);

    // Pass 1: fp32 -> fp16 (x and W)
    constexpr size_t NGROUPS = X_ELEMS / 8 + W_ELEMS / 8;   // 4,456,448
    cvt_kernel<<<(unsigned)(NGROUPS / 512), 512>>>(x, W);

    // Pass 2: fp16 GEMM + bias
    dim3 grid(N_TOK / M_TILE, C_OUT / N_TILE, B_DIM);  // 64 x 4 x 8 = 2048
    fc_gemm_kernel<<<grid, THREADS, SMEM_TOTAL>>>(bias, out);
}